// round 12
// baseline (speedup 1.0000x reference)
#include <cuda_runtime.h>

#define NQ     1224
#define NSTEPS 50
#define NB     1024
#define NROWS  (NB * (NSTEPS - 1))   // 50176 (b, t) pairs, t in [1, 49]
#define ROWVEC (2 * NQ / 4)          // 612 uint4 in a full 2448-float row
#define WARPS_PER_BLOCK 8
#define NBLOCKS (NROWS / WARPS_PER_BLOCK)   // 6272, exact

// Allocation-free scratch. g_sum is reset to 0.0 by the last finishing block
// each run (graph replays start clean); the counter self-resets via
// atomicInc wrap semantics.
__device__ double   g_sum = 0.0;
__device__ unsigned g_counter = 0;

// One warp per (b, t) row of `batch` (t >= 1), contiguous warp->row mapping.
// The 2448-wide row is an exact one-hot: a single 1.0f somewhere in
// [0, 2*NQ). Scan the row as ONE contiguous stream of uint4 (1.0f has
// nonzero bits, 0.0f is all-zero), 512B per warp-step, early-exit on the
// first nonzero via ballot. The hit's global float index g encodes both the
// question q = g mod NQ and the label a = (g < NQ). Then gather
// pred[b, t-1, q] and accumulate the BCE term. pred is in (0,1) by
// construction, so the reference's `p > 0` mask is always satisfied on a
// hit; an all-zero row contributes 0, matching the masked reference.
//
// vs. the lockstep-halves scan: identical expected bytes (E = half the row),
// but a single sequential address stream per warp (better DRAM page
// locality), one load+ballot per step instead of two loads, and finer 512B
// overshoot granularity.
__global__ __launch_bounds__(256) void dkt_loss_kernel(
    const float* __restrict__ pred,
    const float* __restrict__ batch,
    float* __restrict__ out)
{
    const int warp = blockIdx.x * WARPS_PER_BLOCK + (threadIdx.x >> 5);
    const int lane = threadIdx.x & 31;

    int b = warp / (NSTEPS - 1);
    int t = warp - b * (NSTEPS - 1) + 1;   // 1..49

    const uint4* row = (const uint4*)(batch + ((size_t)b * NSTEPS + t) * (size_t)(2 * NQ));
    const float* pred_row = pred + ((size_t)b * NSTEPS + (t - 1)) * (size_t)NQ;

    float contrib = 0.0f;

    #pragma unroll 1
    for (int base = 0; base < ROWVEC; base += 32) {
        int v = base + lane;
        uint4 f = make_uint4(0u, 0u, 0u, 0u);
        if (v < ROWVEC) f = __ldg(row + v);

        unsigned orf = f.x | f.y | f.z | f.w;
        unsigned m = __ballot_sync(0xffffffffu, orf != 0u);
        if (m) {
            if (orf != 0u) {   // at most one lane in the warp: the one-hot owner
                int idx = f.x ? 0 : (f.y ? 1 : (f.z ? 2 : 3));
                int g = 4 * v + idx;             // global column in [0, 2*NQ)
                int corr = (g < NQ);             // which half -> label a
                int q = corr ? g : g - NQ;       // question index
                float p = __ldg(pred_row + q);
                contrib = corr ? logf(p) : logf(1.0f - p);
            }
            break;   // ballot result is warp-uniform: no divergence hazard
        }
    }

    // Warp reduction (at most one lane is nonzero, but reduce anyway).
    #pragma unroll
    for (int o = 16; o; o >>= 1)
        contrib += __shfl_xor_sync(0xffffffffu, contrib, o);

    __shared__ float wsum[WARPS_PER_BLOCK];
    if (lane == 0) wsum[threadIdx.x >> 5] = contrib;
    __syncthreads();

    if (threadIdx.x == 0) {
        float blocksum = 0.0f;
        #pragma unroll
        for (int i = 0; i < WARPS_PER_BLOCK; i++) blocksum += wsum[i];

        // Accumulate in double; overlaps other blocks' scan work.
        atomicAdd(&g_sum, (double)blocksum);
        __threadfence();
        unsigned old = atomicInc(&g_counter, (unsigned)(gridDim.x - 1));
        if (old == gridDim.x - 1) {
            // Last block: all atomicAdds are globally visible (each was fenced
            // before its counter increment). Publish and reset for replay.
            double total = g_sum;
            out[0] = (float)(-total);
            g_sum = 0.0;
        }
    }
}

extern "C" void kernel_launch(void* const* d_in, const int* in_sizes, int n_in,
                              void* d_out, int out_size)
{
    // Identify inputs by element count (robust to metadata ordering):
    // pred  = 1024*50*1224 = 62,668,800
    // batch = 1024*50*2448 = 125,337,600
    const float* pred;
    const float* batch;
    if (in_sizes[0] == NB * NSTEPS * NQ) {
        pred  = (const float*)d_in[0];
        batch = (const float*)d_in[1];
    } else {
        pred  = (const float*)d_in[1];
        batch = (const float*)d_in[0];
    }

    dkt_loss_kernel<<<NBLOCKS, 256>>>(pred, batch, (float*)d_out);
}

// round 16
// speedup vs baseline: 1.3751x; 1.3751x over previous
#include <cuda_runtime.h>

#define NQ     1224
#define NSTEPS 50
#define NB     1024
#define NROWS  (NB * (NSTEPS - 1))   // 50176 (b, t) pairs, t in [1, 49]
#define ROWVEC (2 * NQ / 4)          // 612 uint4 in a full 2448-float row
#define WARPS_PER_BLOCK 8
#define NBLOCKS (NROWS / WARPS_PER_BLOCK)   // 6272, exact

// Allocation-free scratch. g_sum is reset by the last finishing block each
// run (graph replays start clean); the counter self-resets via atomicInc
// wrap semantics.
__device__ double   g_sum = 0.0;
__device__ unsigned g_counter = 0;

// One warp per (b, t) row of `batch` (t >= 1), contiguous warp->row mapping.
// The 2448-wide row is an exact one-hot: a single 1.0f somewhere in
// [0, 2*NQ). Scan the row as ONE contiguous stream in BATCHED 2KB steps:
// 4 back-to-back 512B warp-loads (MLP=4 per serial round-trip, contiguous
// DRAM burst), then a single combined ballot. Early-exit on the first step
// containing the nonzero. The hit's global float index g gives both the
// question q = g mod NQ and the label a = (g < NQ); gather pred[b,t-1,q]
// and accumulate the BCE term. pred is in (0,1) by construction, so the
// reference's `p > 0` mask is always satisfied on a hit; an all-zero row
// contributes 0, matching the masked reference.
__global__ __launch_bounds__(256) void dkt_loss_kernel(
    const float* __restrict__ pred,
    const float* __restrict__ batch,
    float* __restrict__ out)
{
    const int warp = blockIdx.x * WARPS_PER_BLOCK + (threadIdx.x >> 5);
    const int lane = threadIdx.x & 31;

    int b = warp / (NSTEPS - 1);
    int t = warp - b * (NSTEPS - 1) + 1;   // 1..49

    const uint4* row = (const uint4*)(batch + ((size_t)b * NSTEPS + t) * (size_t)(2 * NQ));
    const float* pred_row = pred + ((size_t)b * NSTEPS + (t - 1)) * (size_t)NQ;

    float contrib = 0.0f;

    // 5 steps of 128 uint4 (2KB) cover 612; last step is partial (100).
    #pragma unroll 1
    for (int base = 0; base < ROWVEC; base += 128) {
        const uint4 z = make_uint4(0u, 0u, 0u, 0u);
        uint4 d0 = z, d1 = z, d2 = z, d3 = z;
        int v0 = base + lane;
        int v1 = v0 + 32;
        int v2 = v0 + 64;
        int v3 = v0 + 96;
        // Four independent loads issued back-to-back: 2KB contiguous burst.
        if (v0 < ROWVEC) d0 = __ldg(row + v0);
        if (v1 < ROWVEC) d1 = __ldg(row + v1);
        if (v2 < ROWVEC) d2 = __ldg(row + v2);
        if (v3 < ROWVEC) d3 = __ldg(row + v3);

        unsigned o0 = d0.x | d0.y | d0.z | d0.w;
        unsigned o1 = d1.x | d1.y | d1.z | d1.w;
        unsigned o2 = d2.x | d2.y | d2.z | d2.w;
        unsigned o3 = d3.x | d3.y | d3.z | d3.w;
        unsigned any = o0 | o1 | o2 | o3;

        unsigned m = __ballot_sync(0xffffffffu, any != 0u);
        if (m) {
            if (any != 0u) {   // at most one lane warp-wide: the one-hot owner
                // Exactly one nonzero word exists in the whole row; find it.
                uint4 d; int v;
                if      (o0) { d = d0; v = v0; }
                else if (o1) { d = d1; v = v1; }
                else if (o2) { d = d2; v = v2; }
                else         { d = d3; v = v3; }
                int idx = d.x ? 0 : (d.y ? 1 : (d.z ? 2 : 3));
                int g = 4 * v + idx;            // global column in [0, 2*NQ)
                int corr = (g < NQ);            // which half -> label a
                int q = corr ? g : g - NQ;      // question index
                float p = __ldg(pred_row + q);
                contrib = corr ? logf(p) : logf(1.0f - p);
            }
            break;   // ballot result is warp-uniform: no divergence hazard
        }
    }

    // Warp reduction (at most one lane is nonzero, but reduce anyway).
    #pragma unroll
    for (int o = 16; o; o >>= 1)
        contrib += __shfl_xor_sync(0xffffffffu, contrib, o);

    __shared__ float wsum[WARPS_PER_BLOCK];
    if (lane == 0) wsum[threadIdx.x >> 5] = contrib;
    __syncthreads();

    if (threadIdx.x == 0) {
        float blocksum = 0.0f;
        #pragma unroll
        for (int i = 0; i < WARPS_PER_BLOCK; i++) blocksum += wsum[i];

        // Accumulate in double; overlaps other blocks' scan work.
        atomicAdd(&g_sum, (double)blocksum);
        __threadfence();
        unsigned old = atomicInc(&g_counter, (unsigned)(gridDim.x - 1));
        if (old == gridDim.x - 1) {
            // Last block: all atomicAdds are globally visible (each was
            // fenced before its counter increment). Publish and reset.
            double total = g_sum;
            out[0] = (float)(-total);
            g_sum = 0.0;
        }
    }
}

extern "C" void kernel_launch(void* const* d_in, const int* in_sizes, int n_in,
                              void* d_out, int out_size)
{
    // Identify inputs by element count (robust to metadata ordering):
    // pred  = 1024*50*1224 = 62,668,800
    // batch = 1024*50*2448 = 125,337,600
    const float* pred;
    const float* batch;
    if (in_sizes[0] == NB * NSTEPS * NQ) {
        pred  = (const float*)d_in[0];
        batch = (const float*)d_in[1];
    } else {
        pred  = (const float*)d_in[1];
        batch = (const float*)d_in[0];
    }

    dkt_loss_kernel<<<NBLOCKS, 256>>>(pred, batch, (float*)d_out);
}